// round 1
// baseline (speedup 1.0000x reference)
#include <cuda_runtime.h>
#include <cstdint>
#include <cstddef>

#define NB   32
#define NC   256
#define NHW  3136
#define NWID 56
#define NOC  256
#define NR   64
#define NM1  576   // 9 taps * 64 rank

// Scratch for stage-1 output S[b][tap*64+r][h*56+w]  (231 MB, .bss device global)
__device__ float g_S[(size_t)NB * NM1 * NHW];

// ---------------- packed f32x2 helpers ----------------
__device__ __forceinline__ unsigned long long pack2(float x, float y) {
    unsigned long long r;
    asm("mov.b64 %0, {%1, %2};" : "=l"(r) : "f"(x), "f"(y));
    return r;
}
__device__ __forceinline__ void unpack2(unsigned long long v, float& x, float& y) {
    asm("mov.b64 {%0, %1}, %2;" : "=f"(x), "=f"(y) : "l"(v));
}
__device__ __forceinline__ void ffma2(unsigned long long& d, unsigned long long a, unsigned long long b) {
    asm("fma.rn.f32x2 %0, %1, %2, %0;" : "+l"(d) : "l"(a), "l"(b));
}

// 8 k-steps of the 128x128 tile: 8(m) x 8(n) per thread as 32 packed FMA2 / k-step.
// As2 holds A values duplicated into both f32 lanes ({a,a}); Bs holds raw floats
// whose adjacent pairs are consumed as one f32x2 operand.
__device__ __forceinline__ void mma_tile(const unsigned long long (*As2)[128],
                                         const float (*Bs)[128],
                                         unsigned long long (&acc)[8][4],
                                         int m0, int n0) {
    #pragma unroll
    for (int k = 0; k < 8; k++) {
        unsigned long long a2[8], b2[4];
        ulonglong2 t;
        t = *(const ulonglong2*)&As2[k][m0];      a2[0] = t.x; a2[1] = t.y;
        t = *(const ulonglong2*)&As2[k][m0 + 2];  a2[2] = t.x; a2[3] = t.y;
        t = *(const ulonglong2*)&As2[k][m0 + 64]; a2[4] = t.x; a2[5] = t.y;
        t = *(const ulonglong2*)&As2[k][m0 + 66]; a2[6] = t.x; a2[7] = t.y;
        t = *(const ulonglong2*)&Bs[k][n0];       b2[0] = t.x; b2[1] = t.y;
        t = *(const ulonglong2*)&Bs[k][n0 + 64];  b2[2] = t.x; b2[3] = t.y;
        #pragma unroll
        for (int i = 0; i < 8; i++)
            #pragma unroll
            for (int j = 0; j < 4; j++)
                ffma2(acc[i][j], a2[i], b2[j]);
    }
}

// ================= Stage 1: S_b[576,3136] = Vflat[576,256] @ X_b[256,3136] =================
__global__ __launch_bounds__(256, 2)
void stage1_kernel(const float* __restrict__ x, const float* __restrict__ Vw) {
    __shared__ __align__(16) unsigned long long As2[8][128];
    __shared__ __align__(16) float Bs[8][128];

    const int b     = blockIdx.z;
    const int mBase = blockIdx.y * 128;
    const int pBase = blockIdx.x * 128;
    const float* X = x + (size_t)b * NC * NHW;
    float* S = g_S + (size_t)b * NM1 * NHW;

    const int tid = threadIdx.x;
    const int ty = tid >> 4, tx = tid & 15;
    const int m0 = ty * 4, n0 = tx * 4;

    // loader lane roles
    const int ml = tid >> 1, cSel = (tid & 1) * 4;      // A tile: 128 m x 8 c
    const int cl = tid >> 5, pl = (tid & 31) * 4;       // B tile: 8 c x 128 p
    const bool aValid = (mBase + ml) < NM1;
    const bool bValid = (pBase + pl) < NHW;
    const float* aPtr = Vw + (size_t)(mBase + ml) * NC + cSel;
    const float* bPtr = X + (size_t)cl * NHW + pBase + pl;

    unsigned long long acc[8][4];
    #pragma unroll
    for (int i = 0; i < 8; i++)
        #pragma unroll
        for (int j = 0; j < 4; j++) acc[i][j] = 0ull;

    for (int kt = 0; kt < NC / 8; kt++) {
        float4 av = make_float4(0.f, 0.f, 0.f, 0.f);
        if (aValid) av = *(const float4*)(aPtr + kt * 8);
        float4 bv = make_float4(0.f, 0.f, 0.f, 0.f);
        if (bValid) bv = *(const float4*)(bPtr + (size_t)kt * 8 * NHW);
        __syncthreads();
        As2[cSel + 0][ml] = pack2(av.x, av.x);
        As2[cSel + 1][ml] = pack2(av.y, av.y);
        As2[cSel + 2][ml] = pack2(av.z, av.z);
        As2[cSel + 3][ml] = pack2(av.w, av.w);
        *(float4*)&Bs[cl][pl] = bv;
        __syncthreads();
        mma_tile(As2, Bs, acc, m0, n0);
    }

    #pragma unroll
    for (int ig = 0; ig < 2; ig++)
        #pragma unroll
        for (int i = 0; i < 4; i++) {
            int m = mBase + m0 + ig * 64 + i;
            if (m < NM1) {
                #pragma unroll
                for (int jg = 0; jg < 2; jg++) {
                    int p = pBase + n0 + jg * 64;
                    if (p < NHW) {
                        float4 v;
                        unpack2(acc[ig * 4 + i][jg * 2 + 0], v.x, v.y);
                        unpack2(acc[ig * 4 + i][jg * 2 + 1], v.z, v.w);
                        *(float4*)&S[(size_t)m * NHW + p] = v;
                    }
                }
            }
        }
}

// ========= Stage 2: Y_b[256,3136] = sum_tap U_tap[256,64] @ shift(S_tap,b)[64,3136] =========
__global__ __launch_bounds__(256, 2)
void stage2_kernel(const float* __restrict__ Uw, float* __restrict__ y) {
    __shared__ __align__(16) unsigned long long As2[8][128];
    __shared__ __align__(16) float Bs[8][128];

    const int b     = blockIdx.z;
    const int oBase = blockIdx.y * 128;
    const int pBase = blockIdx.x * 128;
    const float* S = g_S + (size_t)b * NM1 * NHW;
    float* Y = y + (size_t)b * NOC * NHW;

    const int tid = threadIdx.x;
    const int ty = tid >> 4, tx = tid & 15;
    const int m0 = ty * 4, n0 = tx * 4;

    const int ol = tid >> 1, rSel = (tid & 1) * 4;      // A tile: 128 o x 8 r
    const int rl = tid >> 5, pl = (tid & 31) * 4;       // B tile: 8 r x 128 p

    unsigned long long acc[8][4];
    #pragma unroll
    for (int i = 0; i < 8; i++)
        #pragma unroll
        for (int j = 0; j < 4; j++) acc[i][j] = 0ull;

    for (int tap = 0; tap < 9; tap++) {
        const int di = tap / 3 - 1, dj = tap % 3 - 1;
        // Per-thread shifted-gather info for this tap (invariant across k-steps).
        int  off[4];
        bool val[4];
        #pragma unroll
        for (int e = 0; e < 4; e++) {
            int p = pBase + pl + e;
            int h = p / NWID;
            int w = p - h * NWID;
            val[e] = (p < NHW) && ((unsigned)(h + di) < (unsigned)NWID)
                               && ((unsigned)(w + dj) < (unsigned)NWID);
            off[e] = p + di * NWID + dj;
        }
        const float* Stap = S + (size_t)tap * NR * NHW;
        const float* Utap = Uw + (size_t)tap * NOC * NR + (size_t)(oBase + ol) * NR + rSel;

        for (int kt = 0; kt < NR / 8; kt++) {
            float4 av = *(const float4*)(Utap + kt * 8);
            const float* srow = Stap + (size_t)(kt * 8 + rl) * NHW;
            float b0v = val[0] ? srow[off[0]] : 0.f;
            float b1v = val[1] ? srow[off[1]] : 0.f;
            float b2v = val[2] ? srow[off[2]] : 0.f;
            float b3v = val[3] ? srow[off[3]] : 0.f;
            __syncthreads();
            As2[rSel + 0][ol] = pack2(av.x, av.x);
            As2[rSel + 1][ol] = pack2(av.y, av.y);
            As2[rSel + 2][ol] = pack2(av.z, av.z);
            As2[rSel + 3][ol] = pack2(av.w, av.w);
            *(float4*)&Bs[rl][pl] = make_float4(b0v, b1v, b2v, b3v);
            __syncthreads();
            mma_tile(As2, Bs, acc, m0, n0);
        }
    }

    #pragma unroll
    for (int ig = 0; ig < 2; ig++)
        #pragma unroll
        for (int i = 0; i < 4; i++) {
            int o = oBase + m0 + ig * 64 + i;   // always < 256
            #pragma unroll
            for (int jg = 0; jg < 2; jg++) {
                int p = pBase + n0 + jg * 64;
                if (p < NHW) {
                    float4 v;
                    unpack2(acc[ig * 4 + i][jg * 2 + 0], v.x, v.y);
                    unpack2(acc[ig * 4 + i][jg * 2 + 1], v.z, v.w);
                    *(float4*)&Y[(size_t)o * NHW + p] = v;
                }
            }
        }
}

extern "C" void kernel_launch(void* const* d_in, const int* in_sizes, int n_in,
                              void* d_out, int out_size) {
    const float* x = (const float*)d_in[0];   // [32,256,56,56]
    const float* U = (const float*)d_in[1];   // [3,3,256,64]
    const float* V = (const float*)d_in[2];   // [3,3,64,256]
    float* y = (float*)d_out;                 // [32,256,56,56]

    dim3 blk(256);
    dim3 g1((NHW + 127) / 128, (NM1 + 127) / 128, NB);   // 25 x 5 x 32
    stage1_kernel<<<g1, blk>>>(x, V);
    dim3 g2((NHW + 127) / 128, NOC / 128, NB);           // 25 x 2 x 32
    stage2_kernel<<<g2, blk>>>(U, y);
}

// round 3
// speedup vs baseline: 1.4411x; 1.4411x over previous
#include <cuda_runtime.h>
#include <mma.h>
#include <cstdint>
#include <cstddef>

using namespace nvcuda;

#define NB   32
#define NC   256
#define NHW  3136
#define NWID 56
#define NOC  256
#define NR   64
#define NM1  576   // 9 taps * 64 rank

// Device-global scratch (alloc-guard workaround)
__device__ float g_S[(size_t)NB * NM1 * NHW];   // S: [b][m][p]  (231 MB), tf32-rounded
__device__ float g_Vt[(size_t)NM1 * NC];        // V tf32:  [m][c]
__device__ float g_U2[(size_t)NOC * NM1];       // U tf32 repacked: [o][m]

// ---------------- helpers ----------------
__device__ __forceinline__ uint32_t smem_u32(const void* p) {
    uint32_t a;
    asm("{ .reg .u64 t; cvta.to.shared.u64 t, %1; cvt.u32.u64 %0, t; }" : "=r"(a) : "l"(p));
    return a;
}
__device__ __forceinline__ float to_tf32(float x) {
    float r;
    asm("cvt.rna.tf32.f32 %0, %1;" : "=f"(r) : "f"(x));
    return r;
}
__device__ __forceinline__ void cp16(uint32_t dst, const void* src, int szbytes) {
    asm volatile("cp.async.ca.shared.global [%0], [%1], 16, %2;"
                 :: "r"(dst), "l"(src), "r"(szbytes) : "memory");
}
#define CP_COMMIT() asm volatile("cp.async.commit_group;" ::: "memory")
#define CP_WAIT1()  asm volatile("cp.async.wait_group 1;" ::: "memory")
#define CP_WAIT0()  asm volatile("cp.async.wait_group 0;" ::: "memory")

#define LDA 36
#define LDB 136
#define A_OFF(buf) ((buf) * (128 * LDA))
#define B_OFF(buf) (2 * 128 * LDA + (buf) * (32 * LDB))
#define POOL_FLOATS (2 * 128 * LDA + 2 * 32 * LDB)   // 17920 floats = 71680 B

typedef wmma::fragment<wmma::matrix_a, 16, 16, 8, wmma::precision::tf32, wmma::row_major> FragA;
typedef wmma::fragment<wmma::matrix_b, 16, 16, 8, wmma::precision::tf32, wmma::row_major> FragB;
typedef wmma::fragment<wmma::accumulator, 16, 16, 8, float> FragC;

// ======================= prep kernel =======================
__global__ __launch_bounds__(256)
void weights_kernel(const float* __restrict__ U, const float* __restrict__ V) {
    int idx = blockIdx.x * 256 + threadIdx.x;   // < 576*256
    g_Vt[idx] = to_tf32(V[idx]);                // V flat is already [m][c]
    int o = idx / NM1, m = idx - o * NM1;       // U is [tap][o][r] -> U2[o][m]
    g_U2[idx] = to_tf32(U[(size_t)(m >> 6) * NOC * NR + (size_t)o * NR + (m & 63)]);
}

// ======================= Stage 1 =======================
// S[b][m][p] = sum_c Vt[m][c] * X[b][c][p];   M=576(5 tiles), N=3136(25), K=256(8 chunks)
__global__ __launch_bounds__(256, 2)
void gemm1_kernel(const float* __restrict__ x) {
    extern __shared__ float sm[];
    const int t = threadIdx.x, w = t >> 5;
    const int b = blockIdx.z, mBase = blockIdx.x * 128, pBase = blockIdx.y * 128;
    const int warp_m = w & 1, warp_n = w >> 1;
    const float* X = x + (size_t)b * NC * NHW;

    FragC acc[4][2];
    #pragma unroll
    for (int i = 0; i < 4; i++)
        #pragma unroll
        for (int j = 0; j < 2; j++) wmma::fill_fragment(acc[i][j], 0.0f);

    auto fillA = [&](int kBase, int buf) {
        #pragma unroll
        for (int it = 0; it < 4; it++) {
            int idx = it * 256 + t;
            int row = idx >> 3, kg = idx & 7;
            bool v = (mBase + row) < NM1;
            const float* src = v ? g_Vt + (size_t)(mBase + row) * NC + kBase + kg * 4 : g_Vt;
            cp16(smem_u32(sm + A_OFF(buf) + row * LDA + kg * 4), src, v ? 16 : 0);
        }
    };
    auto fillB = [&](int kBase, int buf) {
        #pragma unroll
        for (int it = 0; it < 4; it++) {
            int idx = it * 256 + t;
            int row = idx >> 5, pg = idx & 31;
            bool v = (pBase + pg * 4) < NHW;
            const float* src = v ? X + (size_t)(kBase + row) * NHW + pBase + pg * 4 : X;
            cp16(smem_u32(sm + B_OFF(buf) + row * LDB + pg * 4), src, v ? 16 : 0);
        }
    };

    fillA(0, 0); fillB(0, 0); CP_COMMIT();

    for (int ch = 0; ch < 8; ch++) {
        const int buf = ch & 1;
        if (ch < 7) {
            fillA((ch + 1) * 32, buf ^ 1);
            fillB((ch + 1) * 32, buf ^ 1);
            CP_COMMIT();
            CP_WAIT1();
        } else {
            CP_WAIT0();
        }
        __syncthreads();
        const float* A  = sm + A_OFF(buf);
        const float* Bm = sm + B_OFF(buf);
        #pragma unroll
        for (int kk = 0; kk < 32; kk += 8) {
            FragA a[4];
            FragB bf[2];
            #pragma unroll
            for (int i = 0; i < 4; i++)
                wmma::load_matrix_sync(a[i], A + (warp_m * 64 + i * 16) * LDA + kk, LDA);
            #pragma unroll
            for (int j = 0; j < 2; j++) {
                wmma::load_matrix_sync(bf[j], Bm + kk * LDB + warp_n * 32 + j * 16, LDB);
                #pragma unroll
                for (int e = 0; e < bf[j].num_elements; e++)
                    bf[j].x[e] = wmma::__float_to_tf32(bf[j].x[e]);
            }
            #pragma unroll
            for (int i = 0; i < 4; i++)
                #pragma unroll
                for (int j = 0; j < 2; j++)
                    wmma::mma_sync(acc[i][j], a[i], bf[j], acc[i][j]);
        }
        __syncthreads();
    }

    // epilogue: tf32-round and store to S[b][m][p]
    const int mv = NM1 - mBase, pv = NHW - pBase;
    float* C = g_S + ((size_t)b * NM1 + mBase) * NHW + pBase;
    #pragma unroll
    for (int i = 0; i < 4; i++) {
        if (warp_m * 64 + i * 16 < mv) {
            #pragma unroll
            for (int j = 0; j < 2; j++) {
                if (warp_n * 32 + j * 16 < pv) {
                    #pragma unroll
                    for (int e = 0; e < acc[i][j].num_elements; e++)
                        acc[i][j].x[e] = to_tf32(acc[i][j].x[e]);
                    wmma::store_matrix_sync(
                        C + (size_t)(warp_m * 64 + i * 16) * NHW + warp_n * 32 + j * 16,
                        acc[i][j], NHW, wmma::mem_row_major);
                }
            }
        }
    }
}

// ======================= Stage 2 =======================
// Y[b][o][p] = sum_{tap,r} U2[o][tap*64+r] * S[b][tap*64+r][p+shift]  (edge masked)
__global__ __launch_bounds__(256)
void gemm2_kernel(float* __restrict__ y) {
    extern __shared__ float sm[];
    const int t = threadIdx.x, w = t >> 5;
    const int b = blockIdx.z, oBase = blockIdx.x * 128, pBase = blockIdx.y * 128;
    const int warp_m = w & 1, warp_n = w >> 1;
    const float* S = g_S + (size_t)b * NM1 * NHW;

    // per-thread gather geometry (4 float4 groups per thread)
    int p0[4], h0[4], w0[4];
    #pragma unroll
    for (int it = 0; it < 4; it++) {
        int idx = it * 256 + t;
        int pg = idx & 31;
        p0[it] = pBase + pg * 4;
        h0[it] = p0[it] / NWID;
        w0[it] = p0[it] - h0[it] * NWID;
    }

    FragC acc[4][2];
    #pragma unroll
    for (int i = 0; i < 4; i++)
        #pragma unroll
        for (int j = 0; j < 2; j++) wmma::fill_fragment(acc[i][j], 0.0f);

    auto fillA = [&](int ch, int buf) {
        int kBase = ch * 32;
        #pragma unroll
        for (int it = 0; it < 4; it++) {
            int idx = it * 256 + t;
            int row = idx >> 3, kg = idx & 7;
            cp16(smem_u32(sm + A_OFF(buf) + row * LDA + kg * 4),
                 g_U2 + (size_t)(oBase + row) * NM1 + kBase + kg * 4, 16);
        }
    };
    auto ldgB = [&](int ch, float (*r)[4]) {
        int tap = ch >> 1;
        int di = tap / 3 - 1, dj = tap % 3 - 1;
        int kBase = tap * 64 + (ch & 1) * 32;
        #pragma unroll
        for (int it = 0; it < 4; it++) {
            int idx = it * 256 + t;
            int row = idx >> 5;
            const float* srow = S + (size_t)(kBase + row) * NHW;
            #pragma unroll
            for (int e = 0; e < 4; e++) {
                int p = p0[it] + e;
                bool ok = (p < NHW) && ((unsigned)(h0[it] + di) < (unsigned)NWID)
                                    && ((unsigned)(w0[it] + e + dj) < (unsigned)NWID);
                r[it][e] = ok ? srow[p + di * NWID + dj] : 0.0f;
            }
        }
    };
    auto stsB = [&](float (*r)[4], int buf) {
        #pragma unroll
        for (int it = 0; it < 4; it++) {
            int idx = it * 256 + t;
            int row = idx >> 5, pg = idx & 31;
            *(float4*)&sm[B_OFF(buf) + row * LDB + pg * 4] =
                make_float4(r[it][0], r[it][1], r[it][2], r[it][3]);
        }
    };

    float r0[4][4], r1[4][4];
    ldgB(0, r0);
    fillA(0, 0); CP_COMMIT();
    stsB(r0, 0);

    for (int ch = 0; ch < 18; ch++) {
        const int buf = ch & 1;
        if (ch < 17) {
            ldgB(ch + 1, (ch & 1) ? r0 : r1);
            fillA(ch + 1, buf ^ 1);
            CP_COMMIT();
            CP_WAIT1();
        } else {
            CP_WAIT0();
        }
        __syncthreads();
        const float* A  = sm + A_OFF(buf);
        const float* Bm = sm + B_OFF(buf);
        #pragma unroll
        for (int kk = 0; kk < 32; kk += 8) {
            FragA a[4];
            FragB bf[2];
            #pragma unroll
            for (int i = 0; i < 4; i++)
                wmma::load_matrix_sync(a[i], A + (warp_m * 64 + i * 16) * LDA + kk, LDA);
            #pragma unroll
            for (int j = 0; j < 2; j++)
                wmma::load_matrix_sync(bf[j], Bm + kk * LDB + warp_n * 32 + j * 16, LDB);
            #pragma unroll
            for (int i = 0; i < 4; i++)
                #pragma unroll
                for (int j = 0; j < 2; j++)
                    wmma::mma_sync(acc[i][j], a[i], bf[j], acc[i][j]);
        }
        __syncthreads();
        if (ch < 17) stsB((ch & 1) ? r0 : r1, buf ^ 1);
    }

    // epilogue: store Y (o rows always valid; p masked at last tile)
    const int pv = NHW - pBase;
    float* C = y + ((size_t)b * NOC + oBase) * NHW + pBase;
    #pragma unroll
    for (int i = 0; i < 4; i++)
        #pragma unroll
        for (int j = 0; j < 2; j++)
            if (warp_n * 32 + j * 16 < pv)
                wmma::store_matrix_sync(
                    C + (size_t)(warp_m * 64 + i * 16) * NHW + warp_n * 32 + j * 16,
                    acc[i][j], NHW, wmma::mem_row_major);
}

// ======================= launch =======================
extern "C" void kernel_launch(void* const* d_in, const int* in_sizes, int n_in,
                              void* d_out, int out_size) {
    const float* x = (const float*)d_in[0];   // [32,256,56,56]
    const float* U = (const float*)d_in[1];   // [3,3,256,64]
    const float* V = (const float*)d_in[2];   // [3,3,64,256]
    float* y = (float*)d_out;                 // [32,256,56,56]

    const int dynsmem = POOL_FLOATS * 4;      // 71680 B
    cudaFuncSetAttribute(gemm1_kernel, cudaFuncAttributeMaxDynamicSharedMemorySize, dynsmem);
    cudaFuncSetAttribute(gemm2_kernel, cudaFuncAttributeMaxDynamicSharedMemorySize, dynsmem);

    weights_kernel<<<576, 256>>>(U, V);
    gemm1_kernel<<<dim3(5, 25, 32), 256, dynsmem>>>(x);   // m-tiles fastest: share X tile in L2
    gemm2_kernel<<<dim3(2, 25, 32), 256, dynsmem>>>(y);
}

// round 5
// speedup vs baseline: 2.8702x; 1.9917x over previous
#include <cuda_runtime.h>
#include <cuda_fp16.h>
#include <mma.h>
#include <cstdint>
#include <cstddef>

using namespace nvcuda;

#define NB   32
#define NC   256
#define NHW  3136
#define NWID 56
#define NOC  256
#define NR   64
#define NM1  576   // 9 taps * 64 rank

// Device-global scratch (alloc-guard workaround)
__device__ __half g_Sh[(size_t)NB * NM1 * NHW];   // S:  [b][m][p]  (115 MB) fp16
__device__ __half g_Xh[(size_t)NB * NC * NHW];    // X:  [b][c][p]  (51 MB)  fp16
__device__ __half g_Vh[(size_t)NM1 * NC];         // V:  [m][c]     fp16
__device__ __half g_U2h[(size_t)NOC * NM1];       // U:  [o][m]     fp16

// ---------------- helpers ----------------
__device__ __forceinline__ uint32_t smem_u32(const void* p) {
    uint32_t a;
    asm("{ .reg .u64 t; cvta.to.shared.u64 t, %1; cvt.u32.u64 %0, t; }" : "=r"(a) : "l"(p));
    return a;
}
__device__ __forceinline__ void cp16(uint32_t dst, const void* src, int szbytes) {
    asm volatile("cp.async.ca.shared.global [%0], [%1], 16, %2;"
                 :: "r"(dst), "l"(src), "r"(szbytes) : "memory");
}
#define CP_COMMIT() asm volatile("cp.async.commit_group;" ::: "memory")
#define CP_WAIT1()  asm volatile("cp.async.wait_group 1;" ::: "memory")
#define CP_WAIT0()  asm volatile("cp.async.wait_group 0;" ::: "memory")

// smem layout (halves): A tiles 128x(64+8), B tiles 64x(128+8), double buffered
#define LDA 72
#define LDB 136
#define A_OFF(buf) ((buf) * (128 * LDA))
#define B_OFF(buf) (2 * 128 * LDA + (buf) * (64 * LDB))
#define POOL_HALFS (2 * 128 * LDA + 2 * 64 * LDB)   // 35840 halves = 71680 B

#define LDST 20   // epilogue staging ldm (floats) — MUST be multiple of 4 for wmma

typedef wmma::fragment<wmma::matrix_a, 16, 16, 16, __half, wmma::row_major> FragA;
typedef wmma::fragment<wmma::matrix_b, 16, 16, 16, __half, wmma::row_major> FragB;
typedef wmma::fragment<wmma::accumulator, 16, 16, 16, float> FragC;

// ======================= prep kernels =======================
__global__ __launch_bounds__(256)
void weights_kernel(const float* __restrict__ U, const float* __restrict__ V) {
    int idx = blockIdx.x * 256 + threadIdx.x;   // < 576*256 = 147456
    g_Vh[idx] = __float2half_rn(V[idx]);        // V flat is already [m][c]
    int o = idx / NM1, m = idx - o * NM1;       // U is [tap][o][r] -> U2[o][m]
    g_U2h[idx] = __float2half_rn(U[(size_t)(m >> 6) * NOC * NR + (size_t)o * NR + (m & 63)]);
}

__global__ __launch_bounds__(256)
void convx_kernel(const float* __restrict__ x) {
    size_t i = ((size_t)blockIdx.x * 256 + threadIdx.x) * 4;   // total 25690112, div by 4
    float4 v = *(const float4*)(x + i);
    __half2 a = __floats2half2_rn(v.x, v.y);
    __half2 b = __floats2half2_rn(v.z, v.w);
    *(uint2*)(g_Xh + i) = make_uint2(*(uint32_t*)&a, *(uint32_t*)&b);
}

// ======================= Stage 1 =======================
// S[b][m][p] = sum_c Vh[m][c] * Xh[b][c][p];  M=576(5 tiles), N=3136(25), K=256(4 chunks of 64)
__global__ __launch_bounds__(256, 2)
void gemm1_kernel() {
    extern __shared__ __half sh[];
    const int t = threadIdx.x, w = t >> 5, lane = t & 31;
    const int b = blockIdx.z, mBase = blockIdx.x * 128, pBase = blockIdx.y * 128;
    const int warp_m = w & 1, warp_n = w >> 1;
    const __half* X = g_Xh + (size_t)b * NC * NHW;

    FragC acc[4][2];
    #pragma unroll
    for (int i = 0; i < 4; i++)
        #pragma unroll
        for (int j = 0; j < 2; j++) wmma::fill_fragment(acc[i][j], 0.0f);

    auto fillA = [&](int kBase, int buf) {
        #pragma unroll
        for (int it = 0; it < 4; it++) {           // 128 rows x 8 groups(8 halves)
            int idx = it * 256 + t;
            int row = idx >> 3, kg = idx & 7;
            bool v = (mBase + row) < NM1;
            const __half* src = v ? g_Vh + (size_t)(mBase + row) * NC + kBase + kg * 8 : g_Vh;
            cp16(smem_u32(sh + A_OFF(buf) + row * LDA + kg * 8), src, v ? 16 : 0);
        }
    };
    auto fillB = [&](int kBase, int buf) {
        #pragma unroll
        for (int it = 0; it < 4; it++) {           // 64 rows x 16 groups(8 halves)
            int idx = it * 256 + t;
            int row = idx >> 4, pg = idx & 15;
            bool v = (pBase + pg * 8) < NHW;
            const __half* src = v ? X + (size_t)(kBase + row) * NHW + pBase + pg * 8 : X;
            cp16(smem_u32(sh + B_OFF(buf) + row * LDB + pg * 8), src, v ? 16 : 0);
        }
    };

    fillA(0, 0); fillB(0, 0); CP_COMMIT();

    for (int ch = 0; ch < 4; ch++) {
        const int buf = ch & 1;
        if (ch < 3) {
            fillA((ch + 1) * 64, buf ^ 1);
            fillB((ch + 1) * 64, buf ^ 1);
            CP_COMMIT();
            CP_WAIT1();
        } else {
            CP_WAIT0();
        }
        __syncthreads();
        const __half* A  = sh + A_OFF(buf);
        const __half* Bm = sh + B_OFF(buf);
        #pragma unroll
        for (int kk = 0; kk < 64; kk += 16) {
            FragA a[4];
            FragB bf[2];
            #pragma unroll
            for (int i = 0; i < 4; i++)
                wmma::load_matrix_sync(a[i], A + (warp_m * 64 + i * 16) * LDA + kk, LDA);
            #pragma unroll
            for (int j = 0; j < 2; j++)
                wmma::load_matrix_sync(bf[j], Bm + kk * LDB + warp_n * 32 + j * 16, LDB);
            #pragma unroll
            for (int i = 0; i < 4; i++)
                #pragma unroll
                for (int j = 0; j < 2; j++)
                    wmma::mma_sync(acc[i][j], a[i], bf[j], acc[i][j]);
        }
        __syncthreads();
    }

    // epilogue: stage each 16x16 frag via per-warp smem (ldm=LDST, multiple of 4),
    // convert to fp16, vector-store to S
    const int mv = NM1 - mBase, pv = NHW - pBase;   // multiples of 16 at edges
    float* st = (float*)sh + w * (16 * LDST);       // per-warp 16xLDST staging
    const int srow = lane >> 1, scol = (lane & 1) * 8;
    #pragma unroll
    for (int i = 0; i < 4; i++) {
        int mloc = warp_m * 64 + i * 16;
        if (mloc < mv) {
            #pragma unroll
            for (int j = 0; j < 2; j++) {
                int ploc = warp_n * 32 + j * 16;
                if (ploc < pv) {
                    wmma::store_matrix_sync(st, acc[i][j], LDST, wmma::mem_row_major);
                    __syncwarp();
                    const float* rp = st + srow * LDST + scol;
                    __half2 h0 = __floats2half2_rn(rp[0], rp[1]);
                    __half2 h1 = __floats2half2_rn(rp[2], rp[3]);
                    __half2 h2 = __floats2half2_rn(rp[4], rp[5]);
                    __half2 h3 = __floats2half2_rn(rp[6], rp[7]);
                    uint4 pk = make_uint4(*(uint32_t*)&h0, *(uint32_t*)&h1,
                                          *(uint32_t*)&h2, *(uint32_t*)&h3);
                    *(uint4*)(g_Sh + ((size_t)b * NM1 + mBase + mloc + srow) * NHW
                                     + pBase + ploc + scol) = pk;
                    __syncwarp();
                }
            }
        }
    }
}

// ======================= Stage 2 =======================
// Y[b][o][p] = sum_{tap,r} U2h[o][tap*64+r] * Sh[b][tap*64+r][p+shift]  (edge masked)
__global__ __launch_bounds__(256, 2)
void gemm2_kernel(float* __restrict__ y) {
    extern __shared__ __half sh[];
    const int t = threadIdx.x, w = t >> 5;
    const int b = blockIdx.z, oBase = blockIdx.x * 128, pBase = blockIdx.y * 128;
    const int warp_m = w & 1, warp_n = w >> 1;
    const __half* S = g_Sh + (size_t)b * NM1 * NHW;

    // per-thread gather geometry: pg = t&31 fixed; rows vary with it
    const int pg = t & 31;
    const int p0 = pBase + pg * 4;
    const int h0 = p0 / NWID;
    const int w0 = p0 - h0 * NWID;
    const bool pok = p0 < NHW;

    FragC acc[4][2];
    #pragma unroll
    for (int i = 0; i < 4; i++)
        #pragma unroll
        for (int j = 0; j < 2; j++) wmma::fill_fragment(acc[i][j], 0.0f);

    auto fillA = [&](int tap, int buf) {
        int kBase = tap * 64;
        #pragma unroll
        for (int it = 0; it < 4; it++) {
            int idx = it * 256 + t;
            int row = idx >> 3, kg = idx & 7;
            cp16(smem_u32(sh + A_OFF(buf) + row * LDA + kg * 8),
                 g_U2h + (size_t)(oBase + row) * NM1 + kBase + kg * 8, 16);
        }
    };
    // gather 8 groups of 4 halves into packed regs
    auto ldgB = [&](int tap, uint2 (&r)[8]) {
        const int di = tap / 3 - 1, dj = tap % 3 - 1;
        const int kBase = tap * 64;
        const bool okh = pok && ((unsigned)(h0 + di) < (unsigned)NWID);
        const bool full = okh && (w0 + dj >= 0) && (w0 + 3 + dj <= NWID - 1);
        const int shift = di * NWID + dj;
        #pragma unroll
        for (int it = 0; it < 8; it++) {
            int row = it * 8 + (t >> 5);
            const __half* srow = S + (size_t)(kBase + row) * NHW;
            if (full) {
                if (dj == 0) {
                    r[it] = *(const uint2*)(srow + p0 + shift);      // 8B aligned
                } else {
                    const __half* q = srow + p0 + shift;              // 2B aligned
                    __half2 lo = __halves2half2(q[0], q[1]);
                    __half2 hi = __halves2half2(q[2], q[3]);
                    r[it] = make_uint2(*(uint32_t*)&lo, *(uint32_t*)&hi);
                }
            } else if (okh) {
                __half z = __ushort_as_half(0);
                __half e0 = ((unsigned)(w0 + 0 + dj) < (unsigned)NWID) ? srow[p0 + 0 + shift] : z;
                __half e1 = ((unsigned)(w0 + 1 + dj) < (unsigned)NWID) ? srow[p0 + 1 + shift] : z;
                __half e2 = ((unsigned)(w0 + 2 + dj) < (unsigned)NWID) ? srow[p0 + 2 + shift] : z;
                __half e3 = ((unsigned)(w0 + 3 + dj) < (unsigned)NWID) ? srow[p0 + 3 + shift] : z;
                __half2 lo = __halves2half2(e0, e1);
                __half2 hi = __halves2half2(e2, e3);
                r[it] = make_uint2(*(uint32_t*)&lo, *(uint32_t*)&hi);
            } else {
                r[it] = make_uint2(0u, 0u);
            }
        }
    };
    auto stsB = [&](const uint2 (&r)[8], int buf) {
        #pragma unroll
        for (int it = 0; it < 8; it++) {
            int row = it * 8 + (t >> 5);
            *(uint2*)(sh + B_OFF(buf) + row * LDB + pg * 4) = r[it];
        }
    };

    uint2 r0[8], r1[8];
    ldgB(0, r0);
    fillA(0, 0); CP_COMMIT();
    stsB(r0, 0);

    for (int ch = 0; ch < 9; ch++) {
        const int buf = ch & 1;
        if (ch < 8) {
            ldgB(ch + 1, (ch & 1) ? r0 : r1);
            fillA(ch + 1, buf ^ 1);
            CP_COMMIT();
            CP_WAIT1();
        } else {
            CP_WAIT0();
        }
        __syncthreads();
        const __half* A  = sh + A_OFF(buf);
        const __half* Bm = sh + B_OFF(buf);
        #pragma unroll
        for (int kk = 0; kk < 64; kk += 16) {
            FragA a[4];
            FragB bf[2];
            #pragma unroll
            for (int i = 0; i < 4; i++)
                wmma::load_matrix_sync(a[i], A + (warp_m * 64 + i * 16) * LDA + kk, LDA);
            #pragma unroll
            for (int j = 0; j < 2; j++)
                wmma::load_matrix_sync(bf[j], Bm + kk * LDB + warp_n * 32 + j * 16, LDB);
            #pragma unroll
            for (int i = 0; i < 4; i++)
                #pragma unroll
                for (int j = 0; j < 2; j++)
                    wmma::mma_sync(acc[i][j], a[i], bf[j], acc[i][j]);
        }
        __syncthreads();
        if (ch < 8) stsB((ch & 1) ? r0 : r1, buf ^ 1);
    }

    // epilogue: store Y fp32 (o rows always valid; p frags masked at last tile)
    const int pv = NHW - pBase;
    float* C = y + ((size_t)b * NOC + oBase) * NHW + pBase;
    #pragma unroll
    for (int i = 0; i < 4; i++)
        #pragma unroll
        for (int j = 0; j < 2; j++)
            if (warp_n * 32 + j * 16 < pv)
                wmma::store_matrix_sync(
                    C + (size_t)(warp_m * 64 + i * 16) * NHW + warp_n * 32 + j * 16,
                    acc[i][j], NHW, wmma::mem_row_major);
}

// ======================= launch =======================
extern "C" void kernel_launch(void* const* d_in, const int* in_sizes, int n_in,
                              void* d_out, int out_size) {
    const float* x = (const float*)d_in[0];   // [32,256,56,56]
    const float* U = (const float*)d_in[1];   // [3,3,256,64]
    const float* V = (const float*)d_in[2];   // [3,3,64,256]
    float* y = (float*)d_out;                 // [32,256,56,56]

    const int dynsmem = POOL_HALFS * 2;       // 71680 B
    cudaFuncSetAttribute(gemm1_kernel, cudaFuncAttributeMaxDynamicSharedMemorySize, dynsmem);
    cudaFuncSetAttribute(gemm2_kernel, cudaFuncAttributeMaxDynamicSharedMemorySize, dynsmem);

    weights_kernel<<<576, 256>>>(U, V);
    convx_kernel<<<(NB * NC * NHW) / (256 * 4), 256>>>(x);
    gemm1_kernel<<<dim3(5, 25, 32), 256, dynsmem>>>();    // m fastest: share X tile in L2
    gemm2_kernel<<<dim3(2, 25, 32), 256, dynsmem>>>(y);   // o fastest: share S rows in L2
}

// round 6
// speedup vs baseline: 6.0729x; 2.1158x over previous
#include <cuda_runtime.h>
#include <cuda_fp16.h>
#include <mma.h>
#include <cstdint>
#include <cstddef>

using namespace nvcuda;

#define NB   32
#define NC   256
#define NHW  3136
#define NWID 56
#define NOC  256
#define NR   64
#define NM1  576   // 9 taps * 64 rank

// Device-global scratch (alloc-guard workaround)
__device__ __half g_St[(size_t)NB * NHW * NM1];   // S transposed: [b][p][m] (115 MB) fp16
__device__ __half g_Xh[(size_t)NB * NC * NHW];    // X: [b][c][p] (51 MB) fp16
__device__ __half g_Vh[(size_t)NM1 * NC];         // V: [m][c] fp16
__device__ __half g_U2h[(size_t)NOC * NM1];       // U: [o][m] fp16

// ---------------- helpers ----------------
__device__ __forceinline__ uint32_t smem_u32(const void* p) {
    uint32_t a;
    asm("{ .reg .u64 t; cvta.to.shared.u64 t, %1; cvt.u32.u64 %0, t; }" : "=r"(a) : "l"(p));
    return a;
}
__device__ __forceinline__ void cp16(uint32_t dst, const void* src, int szbytes) {
    asm volatile("cp.async.ca.shared.global [%0], [%1], 16, %2;"
                 :: "r"(dst), "l"(src), "r"(szbytes) : "memory");
}
#define CP_COMMIT() asm volatile("cp.async.commit_group;" ::: "memory")
#define CP_WAIT1()  asm volatile("cp.async.wait_group 1;" ::: "memory")
#define CP_WAIT0()  asm volatile("cp.async.wait_group 0;" ::: "memory")

// ---- gemm1 smem layout (halves): A 128x72, B 64x136, double buffered ----
#define LDA 72
#define LDB 136
#define A_OFF(buf) ((buf) * (128 * LDA))
#define B_OFF(buf) (2 * 128 * LDA + (buf) * (64 * LDB))

// ---- gemm2 smem layout (halves): A 128x72, B 128x72, double buffered ----
#define LDA2 72
#define A2_OFF(buf) ((buf) * (128 * LDA2))
#define B2_OFF(buf) (2 * 128 * LDA2 + (buf) * (128 * LDA2))

#define DYNSMEM 73728   // 4 * 128 * 72 halves = 73728 B (covers gemm1 too)
#define LDT 132         // gemm1 epilogue fp32 staging pitch (mult of 4); 128*132*4=67584 B

typedef wmma::fragment<wmma::matrix_a, 16, 16, 16, __half, wmma::row_major> FragA;
typedef wmma::fragment<wmma::matrix_b, 16, 16, 16, __half, wmma::row_major> FragB;
typedef wmma::fragment<wmma::matrix_b, 16, 16, 16, __half, wmma::col_major> FragBc;
typedef wmma::fragment<wmma::accumulator, 16, 16, 16, float> FragC;

// ======================= prep kernels =======================
__global__ __launch_bounds__(256)
void weights_kernel(const float* __restrict__ U, const float* __restrict__ V) {
    int idx = blockIdx.x * 256 + threadIdx.x;   // < 576*256 = 147456
    g_Vh[idx] = __float2half_rn(V[idx]);        // V flat is already [m][c]
    int o = idx / NM1, m = idx - o * NM1;       // U is [tap][o][r] -> U2[o][m]
    g_U2h[idx] = __float2half_rn(U[(size_t)(m >> 6) * NOC * NR + (size_t)o * NR + (m & 63)]);
}

__global__ __launch_bounds__(256)
void convx_kernel(const float* __restrict__ x) {
    size_t i = ((size_t)blockIdx.x * 256 + threadIdx.x) * 4;   // total 25690112, div by 4
    float4 v = *(const float4*)(x + i);
    __half2 a = __floats2half2_rn(v.x, v.y);
    __half2 b = __floats2half2_rn(v.z, v.w);
    *(uint2*)(g_Xh + i) = make_uint2(*(uint32_t*)&a, *(uint32_t*)&b);
}

// ======================= Stage 1 =======================
// S_t[b][p][m] = sum_c Vh[m][c] * Xh[b][c][p];  M=576(5 tiles), N=3136(25), K=256(4x64)
__global__ __launch_bounds__(256, 2)
void gemm1_kernel() {
    extern __shared__ __half sh[];
    const int t = threadIdx.x, w = t >> 5;
    const int b = blockIdx.z, mBase = blockIdx.x * 128, pBase = blockIdx.y * 128;
    const int warp_m = w & 1, warp_n = w >> 1;
    const __half* X = g_Xh + (size_t)b * NC * NHW;

    FragC acc[4][2];
    #pragma unroll
    for (int i = 0; i < 4; i++)
        #pragma unroll
        for (int j = 0; j < 2; j++) wmma::fill_fragment(acc[i][j], 0.0f);

    auto fillA = [&](int kBase, int buf) {
        #pragma unroll
        for (int it = 0; it < 4; it++) {           // 128 rows x 8 groups of 8 halves
            int idx = it * 256 + t;
            int row = idx >> 3, kg = idx & 7;
            bool v = (mBase + row) < NM1;
            const __half* src = v ? g_Vh + (size_t)(mBase + row) * NC + kBase + kg * 8 : g_Vh;
            cp16(smem_u32(sh + A_OFF(buf) + row * LDA + kg * 8), src, v ? 16 : 0);
        }
    };
    auto fillB = [&](int kBase, int buf) {
        #pragma unroll
        for (int it = 0; it < 4; it++) {           // 64 rows x 16 groups of 8 halves
            int idx = it * 256 + t;
            int row = idx >> 4, pg = idx & 15;
            bool v = (pBase + pg * 8) < NHW;
            const __half* src = v ? X + (size_t)(kBase + row) * NHW + pBase + pg * 8 : X;
            cp16(smem_u32(sh + B_OFF(buf) + row * LDB + pg * 8), src, v ? 16 : 0);
        }
    };

    fillA(0, 0); fillB(0, 0); CP_COMMIT();

    for (int ch = 0; ch < 4; ch++) {
        const int buf = ch & 1;
        if (ch < 3) {
            fillA((ch + 1) * 64, buf ^ 1);
            fillB((ch + 1) * 64, buf ^ 1);
            CP_COMMIT();
            CP_WAIT1();
        } else {
            CP_WAIT0();
        }
        __syncthreads();
        const __half* A  = sh + A_OFF(buf);
        const __half* Bm = sh + B_OFF(buf);
        #pragma unroll
        for (int kk = 0; kk < 64; kk += 16) {
            FragA a[4];
            FragB bf[2];
            #pragma unroll
            for (int i = 0; i < 4; i++)
                wmma::load_matrix_sync(a[i], A + (warp_m * 64 + i * 16) * LDA + kk, LDA);
            #pragma unroll
            for (int j = 0; j < 2; j++)
                wmma::load_matrix_sync(bf[j], Bm + kk * LDB + warp_n * 32 + j * 16, LDB);
            #pragma unroll
            for (int i = 0; i < 4; i++)
                #pragma unroll
                for (int j = 0; j < 2; j++)
                    wmma::mma_sync(acc[i][j], a[i], bf[j], acc[i][j]);
        }
        __syncthreads();
    }

    // epilogue: col-major frag store -> smem T[p][m] (fp32) -> fp16 coalesced S_t writes
    float* T = (float*)sh;
    #pragma unroll
    for (int i = 0; i < 4; i++)
        #pragma unroll
        for (int j = 0; j < 2; j++)
            wmma::store_matrix_sync(T + (size_t)(warp_n * 32 + j * 16) * LDT + warp_m * 64 + i * 16,
                                    acc[i][j], LDT, wmma::mem_col_major);
    __syncthreads();
    const int mv = NM1 - mBase, pv = NHW - pBase;   // multiples of 64
    const int m8 = (t & 15) * 8;
    const bool mok = m8 < mv;
    #pragma unroll
    for (int it = 0; it < 8; it++) {
        int pl = it * 16 + (t >> 4);
        if (mok && pl < pv) {
            const float* rp = T + (size_t)pl * LDT + m8;
            __half2 h0 = __floats2half2_rn(rp[0], rp[1]);
            __half2 h1 = __floats2half2_rn(rp[2], rp[3]);
            __half2 h2 = __floats2half2_rn(rp[4], rp[5]);
            __half2 h3 = __floats2half2_rn(rp[6], rp[7]);
            uint4 pk = make_uint4(*(uint32_t*)&h0, *(uint32_t*)&h1,
                                  *(uint32_t*)&h2, *(uint32_t*)&h3);
            *(uint4*)(g_St + ((size_t)b * NHW + pBase + pl) * NM1 + mBase + m8) = pk;
        }
    }
}

// ======================= Stage 2 =======================
// Y[b][o][p] = sum_{tap,r} U2h[o][tap*64+r] * S_t[b][p+shift][tap*64+r]  (row-masked)
__global__ __launch_bounds__(256, 2)
void gemm2_kernel(float* __restrict__ y) {
    extern __shared__ __half sh[];
    const int t = threadIdx.x, w = t >> 5;
    const int b = blockIdx.z, oBase = blockIdx.x * 128, pBase = blockIdx.y * 128;
    const int warp_m = w & 1, warp_n = w >> 1;
    const __half* S = g_St + (size_t)b * NHW * NM1;

    // per-thread row geometry for the 4 B-rows this thread fills (constant over taps)
    int pr[4], hr[4], wr[4];
    #pragma unroll
    for (int it = 0; it < 4; it++) {
        int row = it * 32 + (t >> 3);
        pr[it] = pBase + row;
        hr[it] = pr[it] / NWID;
        wr[it] = pr[it] - hr[it] * NWID;
    }
    const int kg8 = (t & 7) * 8;

    FragC acc[4][2];
    #pragma unroll
    for (int i = 0; i < 4; i++)
        #pragma unroll
        for (int j = 0; j < 2; j++) wmma::fill_fragment(acc[i][j], 0.0f);

    auto fill = [&](int tap, int buf) {
        const int kBase = tap * 64;
        const int di = tap / 3 - 1, dj = tap % 3 - 1;
        const int shift = di * NWID + dj;
        #pragma unroll
        for (int it = 0; it < 4; it++) {           // A: 128 o-rows x 8 groups
            int row = it * 32 + (t >> 3);
            cp16(smem_u32(sh + A2_OFF(buf) + row * LDA2 + kg8),
                 g_U2h + (size_t)(oBase + row) * NM1 + kBase + kg8, 16);
        }
        #pragma unroll
        for (int it = 0; it < 4; it++) {           // B: 128 p-rows x 8 groups (m contiguous)
            int row = it * 32 + (t >> 3);
            bool ok = (pr[it] < NHW) && ((unsigned)(hr[it] + di) < (unsigned)NWID)
                                     && ((unsigned)(wr[it] + dj) < (unsigned)NWID);
            const __half* src = ok ? S + (size_t)(pr[it] + shift) * NM1 + kBase + kg8 : g_U2h;
            cp16(smem_u32(sh + B2_OFF(buf) + row * LDA2 + kg8), src, ok ? 16 : 0);
        }
    };

    fill(0, 0); CP_COMMIT();

    for (int ch = 0; ch < 9; ch++) {
        const int buf = ch & 1;
        if (ch < 8) {
            fill(ch + 1, buf ^ 1);
            CP_COMMIT();
            CP_WAIT1();
        } else {
            CP_WAIT0();
        }
        __syncthreads();
        const __half* A  = sh + A2_OFF(buf);
        const __half* Bm = sh + B2_OFF(buf);
        #pragma unroll
        for (int kk = 0; kk < 64; kk += 16) {
            FragA a[4];
            FragBc bf[2];
            #pragma unroll
            for (int i = 0; i < 4; i++)
                wmma::load_matrix_sync(a[i], A + (warp_m * 64 + i * 16) * LDA2 + kk, LDA2);
            #pragma unroll
            for (int j = 0; j < 2; j++)
                wmma::load_matrix_sync(bf[j], Bm + (size_t)(warp_n * 32 + j * 16) * LDA2 + kk, LDA2);
            #pragma unroll
            for (int i = 0; i < 4; i++)
                #pragma unroll
                for (int j = 0; j < 2; j++)
                    wmma::mma_sync(acc[i][j], a[i], bf[j], acc[i][j]);
        }
        __syncthreads();
    }

    // epilogue: store Y fp32 (o rows always valid; p frags masked at last tile)
    const int pv = NHW - pBase;
    float* C = y + ((size_t)b * NOC + oBase) * NHW + pBase;
    #pragma unroll
    for (int i = 0; i < 4; i++)
        #pragma unroll
        for (int j = 0; j < 2; j++)
            if (warp_n * 32 + j * 16 < pv)
                wmma::store_matrix_sync(
                    C + (size_t)(warp_m * 64 + i * 16) * NHW + warp_n * 32 + j * 16,
                    acc[i][j], NHW, wmma::mem_row_major);
}

// ======================= launch =======================
extern "C" void kernel_launch(void* const* d_in, const int* in_sizes, int n_in,
                              void* d_out, int out_size) {
    const float* x = (const float*)d_in[0];   // [32,256,56,56]
    const float* U = (const float*)d_in[1];   // [3,3,256,64]
    const float* V = (const float*)d_in[2];   // [3,3,64,256]
    float* y = (float*)d_out;                 // [32,256,56,56]

    cudaFuncSetAttribute(gemm1_kernel, cudaFuncAttributeMaxDynamicSharedMemorySize, DYNSMEM);
    cudaFuncSetAttribute(gemm2_kernel, cudaFuncAttributeMaxDynamicSharedMemorySize, DYNSMEM);

    weights_kernel<<<576, 256>>>(U, V);
    convx_kernel<<<(NB * NC * NHW) / (256 * 4), 256>>>(x);
    gemm1_kernel<<<dim3(5, 25, 32), 256, DYNSMEM>>>();    // m fastest: share X tile in L2
    gemm2_kernel<<<dim3(2, 25, 32), 256, DYNSMEM>>>(y);   // o fastest: share S rows in L2
}

// round 7
// speedup vs baseline: 6.0792x; 1.0010x over previous
#include <cuda_runtime.h>
#include <cuda_fp16.h>
#include <mma.h>
#include <cstdint>
#include <cstddef>

using namespace nvcuda;

#define NB   32
#define NC   256
#define NHW  3136
#define NWID 56
#define NOC  256
#define NR   64
#define NM1  576   // 9 taps * 64 rank

// Device-global scratch (alloc-guard workaround)
__device__ __half g_St[(size_t)NB * NHW * NM1];   // S transposed: [b][p][m] (115 MB) fp16
__device__ __half g_Xh[(size_t)NB * NC * NHW];    // X: [b][c][p] (51 MB) fp16
__device__ __half g_Vh[(size_t)NM1 * NC];         // V: [m][c] fp16
__device__ __half g_U2h[(size_t)NOC * NM1];       // U: [o][m] fp16

// ---------------- helpers ----------------
__device__ __forceinline__ uint32_t smem_u32(const void* p) {
    uint32_t a;
    asm("{ .reg .u64 t; cvta.to.shared.u64 t, %1; cvt.u32.u64 %0, t; }" : "=r"(a) : "l"(p));
    return a;
}
__device__ __forceinline__ void cp16(uint32_t dst, const void* src, int szbytes) {
    asm volatile("cp.async.ca.shared.global [%0], [%1], 16, %2;"
                 :: "r"(dst), "l"(src), "r"(szbytes) : "memory");
}
#define CP_COMMIT() asm volatile("cp.async.commit_group;" ::: "memory")
#define CP_WAIT1()  asm volatile("cp.async.wait_group 1;" ::: "memory")
#define CP_WAIT0()  asm volatile("cp.async.wait_group 0;" ::: "memory")

// ---- gemm1 smem (halves): A 128x72, B 64x136, double buffered ----
#define LDA 72
#define LDB 136
#define A_OFF(buf) ((buf) * (128 * LDA))
#define B_OFF(buf) (2 * 128 * LDA + (buf) * (64 * LDB))
#define DYNSMEM1 73728      // mainloop 71680 B; epilogue T 128*132*4 = 67584 B
#define LDT 132             // gemm1 epilogue fp32 staging pitch (mult of 4)

// ---- gemm2 smem (halves): A 256x72, B 128x72, double buffered ----
#define LDA2 72
#define A2_OFF(buf) ((buf) * (256 * LDA2))
#define B2_OFF(buf) (2 * 256 * LDA2 + (buf) * (128 * LDA2))
#define DYNSMEM2 ((2 * 256 * LDA2 + 2 * 128 * LDA2) * 2)   // 110592 B

typedef wmma::fragment<wmma::matrix_a, 16, 16, 16, __half, wmma::row_major> FragA;
typedef wmma::fragment<wmma::matrix_b, 16, 16, 16, __half, wmma::row_major> FragB;
typedef wmma::fragment<wmma::matrix_b, 16, 16, 16, __half, wmma::col_major> FragBc;
typedef wmma::fragment<wmma::accumulator, 16, 16, 16, float> FragC;

// ======================= prep kernels =======================
__global__ __launch_bounds__(256)
void weights_kernel(const float* __restrict__ U, const float* __restrict__ V) {
    int idx = blockIdx.x * 256 + threadIdx.x;   // < 576*256 = 147456
    g_Vh[idx] = __float2half_rn(V[idx]);        // V flat is already [m][c]
    int o = idx / NM1, m = idx - o * NM1;       // U is [tap][o][r] -> U2[o][m]
    g_U2h[idx] = __float2half_rn(U[(size_t)(m >> 6) * NOC * NR + (size_t)o * NR + (m & 63)]);
}

__global__ __launch_bounds__(256)
void convx_kernel(const float* __restrict__ x) {
    size_t i = ((size_t)blockIdx.x * 256 + threadIdx.x) * 4;   // total 25690112, div by 4
    float4 v = *(const float4*)(x + i);
    __half2 a = __floats2half2_rn(v.x, v.y);
    __half2 b = __floats2half2_rn(v.z, v.w);
    *(uint2*)(g_Xh + i) = make_uint2(*(uint32_t*)&a, *(uint32_t*)&b);
}

// ======================= Stage 1 =======================
// S_t[b][p][m] = sum_c Vh[m][c] * Xh[b][c][p];  4 warps, warp tile 64x64
__global__ __launch_bounds__(128, 2)
void gemm1_kernel() {
    extern __shared__ __half sh[];
    const int t = threadIdx.x, w = t >> 5;
    const int b = blockIdx.z, mBase = blockIdx.x * 128, pBase = blockIdx.y * 128;
    const int warp_m = w & 1, warp_n = w >> 1;
    const __half* X = g_Xh + (size_t)b * NC * NHW;

    FragC acc[4][4];
    #pragma unroll
    for (int i = 0; i < 4; i++)
        #pragma unroll
        for (int j = 0; j < 4; j++) wmma::fill_fragment(acc[i][j], 0.0f);

    auto fillA = [&](int kBase, int buf) {
        #pragma unroll
        for (int it = 0; it < 8; it++) {           // 128 rows x 8 groups of 8 halves
            int idx = it * 128 + t;
            int row = idx >> 3, kg = idx & 7;
            bool v = (mBase + row) < NM1;
            const __half* src = v ? g_Vh + (size_t)(mBase + row) * NC + kBase + kg * 8 : g_Vh;
            cp16(smem_u32(sh + A_OFF(buf) + row * LDA + kg * 8), src, v ? 16 : 0);
        }
    };
    auto fillB = [&](int kBase, int buf) {
        #pragma unroll
        for (int it = 0; it < 8; it++) {           // 64 rows x 16 groups of 8 halves
            int idx = it * 128 + t;
            int row = idx >> 4, pg = idx & 15;
            bool v = (pBase + pg * 8) < NHW;
            const __half* src = v ? X + (size_t)(kBase + row) * NHW + pBase + pg * 8 : X;
            cp16(smem_u32(sh + B_OFF(buf) + row * LDB + pg * 8), src, v ? 16 : 0);
        }
    };

    fillA(0, 0); fillB(0, 0); CP_COMMIT();

    for (int ch = 0; ch < 4; ch++) {
        const int buf = ch & 1;
        if (ch < 3) {
            fillA((ch + 1) * 64, buf ^ 1);
            fillB((ch + 1) * 64, buf ^ 1);
            CP_COMMIT();
            CP_WAIT1();
        } else {
            CP_WAIT0();
        }
        __syncthreads();
        const __half* A  = sh + A_OFF(buf);
        const __half* Bm = sh + B_OFF(buf);
        #pragma unroll
        for (int kk = 0; kk < 64; kk += 16) {
            FragA a[4];
            FragB bf[4];
            #pragma unroll
            for (int i = 0; i < 4; i++)
                wmma::load_matrix_sync(a[i], A + (warp_m * 64 + i * 16) * LDA + kk, LDA);
            #pragma unroll
            for (int j = 0; j < 4; j++)
                wmma::load_matrix_sync(bf[j], Bm + kk * LDB + warp_n * 64 + j * 16, LDB);
            #pragma unroll
            for (int i = 0; i < 4; i++)
                #pragma unroll
                for (int j = 0; j < 4; j++)
                    wmma::mma_sync(acc[i][j], a[i], bf[j], acc[i][j]);
        }
        __syncthreads();
    }

    // epilogue: col-major frag store -> smem T[p][m] (fp32) -> fp16 coalesced S_t writes
    float* T = (float*)sh;
    #pragma unroll
    for (int i = 0; i < 4; i++)
        #pragma unroll
        for (int j = 0; j < 4; j++)
            wmma::store_matrix_sync(T + (size_t)(warp_n * 64 + j * 16) * LDT + warp_m * 64 + i * 16,
                                    acc[i][j], LDT, wmma::mem_col_major);
    __syncthreads();
    const int mv = NM1 - mBase, pv = NHW - pBase;   // multiples of 64
    const int m8 = (t & 15) * 8;
    const bool mok = m8 < mv;
    #pragma unroll
    for (int it = 0; it < 16; it++) {
        int pl = it * 8 + (t >> 4);
        if (mok && pl < pv) {
            const float* rp = T + (size_t)pl * LDT + m8;
            __half2 h0 = __floats2half2_rn(rp[0], rp[1]);
            __half2 h1 = __floats2half2_rn(rp[2], rp[3]);
            __half2 h2 = __floats2half2_rn(rp[4], rp[5]);
            __half2 h3 = __floats2half2_rn(rp[6], rp[7]);
            uint4 pk = make_uint4(*(uint32_t*)&h0, *(uint32_t*)&h1,
                                  *(uint32_t*)&h2, *(uint32_t*)&h3);
            *(uint4*)(g_St + ((size_t)b * NHW + pBase + pl) * NM1 + mBase + m8) = pk;
        }
    }
}

// ======================= Stage 2 =======================
// Y[b][o][p] = sum_{tap,r} U2h[o][k] * S_t[b][p+shift][k]; CTA 256(o)x128(p), 8 warps 64x64
__global__ __launch_bounds__(256, 1)
void gemm2_kernel(float* __restrict__ y) {
    extern __shared__ __half sh[];
    const int t = threadIdx.x, w = t >> 5;
    const int b = blockIdx.z, pBase = blockIdx.y * 128;
    const int warp_m = w >> 1, warp_n = w & 1;    // 4 x 2 grid of 64x64 tiles
    const __half* S = g_St + (size_t)b * NHW * NM1;

    // per-thread row geometry for the 4 B-rows this thread fills (constant over taps)
    int pr[4], hr[4], wr[4];
    #pragma unroll
    for (int it = 0; it < 4; it++) {
        int row = it * 32 + (t >> 3);
        pr[it] = pBase + row;
        hr[it] = pr[it] / NWID;
        wr[it] = pr[it] - hr[it] * NWID;
    }
    const int kg8 = (t & 7) * 8;

    FragC acc[4][4];
    #pragma unroll
    for (int i = 0; i < 4; i++)
        #pragma unroll
        for (int j = 0; j < 4; j++) wmma::fill_fragment(acc[i][j], 0.0f);

    auto fill = [&](int tap, int buf) {
        const int kBase = tap * 64;
        const int di = tap / 3 - 1, dj = tap % 3 - 1;
        const int shift = di * NWID + dj;
        #pragma unroll
        for (int it = 0; it < 8; it++) {           // A: 256 o-rows x 8 groups
            int row = it * 32 + (t >> 3);
            cp16(smem_u32(sh + A2_OFF(buf) + row * LDA2 + kg8),
                 g_U2h + (size_t)row * NM1 + kBase + kg8, 16);
        }
        #pragma unroll
        for (int it = 0; it < 4; it++) {           // B: 128 p-rows x 8 groups (m contiguous)
            int row = it * 32 + (t >> 3);
            bool ok = (pr[it] < NHW) && ((unsigned)(hr[it] + di) < (unsigned)NWID)
                                     && ((unsigned)(wr[it] + dj) < (unsigned)NWID);
            const __half* src = ok ? S + (size_t)(pr[it] + shift) * NM1 + kBase + kg8 : g_U2h;
            cp16(smem_u32(sh + B2_OFF(buf) + row * LDA2 + kg8), src, ok ? 16 : 0);
        }
    };

    fill(0, 0); CP_COMMIT();

    for (int ch = 0; ch < 9; ch++) {
        const int buf = ch & 1;
        if (ch < 8) {
            fill(ch + 1, buf ^ 1);
            CP_COMMIT();
            CP_WAIT1();
        } else {
            CP_WAIT0();
        }
        __syncthreads();
        const __half* A  = sh + A2_OFF(buf);
        const __half* Bm = sh + B2_OFF(buf);
        #pragma unroll
        for (int kk = 0; kk < 64; kk += 16) {
            FragA a[4];
            FragBc bf[4];
            #pragma unroll
            for (int i = 0; i < 4; i++)
                wmma::load_matrix_sync(a[i], A + (warp_m * 64 + i * 16) * LDA2 + kk, LDA2);
            #pragma unroll
            for (int j = 0; j < 4; j++)
                wmma::load_matrix_sync(bf[j], Bm + (size_t)(warp_n * 64 + j * 16) * LDA2 + kk, LDA2);
            #pragma unroll
            for (int i = 0; i < 4; i++)
                #pragma unroll
                for (int j = 0; j < 4; j++)
                    wmma::mma_sync(acc[i][j], a[i], bf[j], acc[i][j]);
        }
        __syncthreads();
    }

    // epilogue: store Y fp32 (o rows always valid; p frags masked at last tile)
    const int pv = NHW - pBase;
    float* C = y + (size_t)b * NOC * NHW + pBase;
    #pragma unroll
    for (int i = 0; i < 4; i++)
        #pragma unroll
        for (int j = 0; j < 4; j++)
            if (warp_n * 64 + j * 16 < pv)
                wmma::store_matrix_sync(
                    C + (size_t)(warp_m * 64 + i * 16) * NHW + warp_n * 64 + j * 16,
                    acc[i][j], NHW, wmma::mem_row_major);
}

// ======================= launch =======================
extern "C" void kernel_launch(void* const* d_in, const int* in_sizes, int n_in,
                              void* d_out, int out_size) {
    const float* x = (const float*)d_in[0];   // [32,256,56,56]
    const float* U = (const float*)d_in[1];   // [3,3,256,64]
    const float* V = (const float*)d_in[2];   // [3,3,64,256]
    float* y = (float*)d_out;                 // [32,256,56,56]

    cudaFuncSetAttribute(gemm1_kernel, cudaFuncAttributeMaxDynamicSharedMemorySize, DYNSMEM1);
    cudaFuncSetAttribute(gemm2_kernel, cudaFuncAttributeMaxDynamicSharedMemorySize, DYNSMEM2);

    weights_kernel<<<576, 256>>>(U, V);
    convx_kernel<<<(NB * NC * NHW) / (256 * 4), 256>>>(x);
    gemm1_kernel<<<dim3(5, 25, 32), 128, DYNSMEM1>>>();   // m fastest: share X tile in L2
    gemm2_kernel<<<dim3(1, 25, 32), 256, DYNSMEM2>>>(y);  // one CTA covers all 256 o
}